// round 10
// baseline (speedup 1.0000x reference)
#include <cuda_runtime.h>
#include <math_constants.h>

typedef unsigned long long u64;
typedef unsigned int u32;

// Problem constants
#define Bb 8
#define Ll 256
#define Aa 15
#define Kk 9
#define TB 16
#define NTILES 136                   // triangular 16x16 tiles per batch
#define KNN_PER_B 32                 // knn CTAs per batch (8 warps each -> 256 rows*2 types)
#define GROUP (NTILES + KNN_PER_B)   // 168 CTAs per batch group
#define FILL_CTAS 680                // N_OUT/4/256 float4 fills
#define TOTAL_CTAS (Bb * GROUP + FILL_CTAS)   // 2024

// Output layout (float32, concatenated flattened tuple)
#define OFF_BATCH   30720
#define OFF_EDGES   32768
#define OFF_ATTR    106496
#define N_OUT       696320
#define EDGES_HALF  18432
#define EDGES_ROW   36864

// Scratch
__device__ float g_d2min[Bb * Ll * Ll];
__device__ u32   g_cnt[Bb];        // dist tiles completed per batch
__device__ u32   g_done[Bb];       // knn CTAs completed per batch (for reset)

static __device__ __forceinline__ u32 ld_acquire(const u32* p) {
    u32 v; asm volatile("ld.acquire.gpu.u32 %0, [%1];" : "=r"(v) : "l"(p) : "memory");
    return v;
}

#define CE(x, y) { u64 aa_ = x, bb_ = y; bool g_ = aa_ > bb_; x = g_ ? bb_ : aa_; y = g_ ? aa_ : bb_; }
#define SORT8(q) \
    CE(q[0],q[1]) CE(q[2],q[3]) CE(q[4],q[5]) CE(q[6],q[7]) \
    CE(q[0],q[2]) CE(q[1],q[3]) CE(q[4],q[6]) CE(q[5],q[7]) \
    CE(q[1],q[2]) CE(q[5],q[6]) \
    CE(q[0],q[4]) CE(q[1],q[5]) CE(q[2],q[6]) CE(q[3],q[7]) \
    CE(q[2],q[4]) CE(q[3],q[5]) \
    CE(q[1],q[2]) CE(q[3],q[4]) CE(q[5],q[6])

// ---------------------------------------------------------------------------
// ONE fused kernel, per-batch interleaved dispatch order:
//   [dist_b0 x136 | knn_b0 x32 | dist_b1 | knn_b1 | ... | fill x680]
// knn_b dispatches right after dist_b -> short spin, overlaps dist_{b+1}.
// fill dispatches last, filling the drain wave. knn is the SOLE writer of the
// dst-edge region.
// ---------------------------------------------------------------------------
__global__ void __launch_bounds__(256) fused_kernel(const float* __restrict__ pos,
                                                    const int* __restrict__ frag,
                                                    const float* __restrict__ edge_emb,
                                                    float* __restrict__ out) {
    const int bid = blockIdx.x;
    const int t   = threadIdx.x;

    if (bid < Bb * GROUP) {
        const int b   = bid / GROUP;
        const int sub = bid % GROUP;

        if (sub < NTILES) {
            // ================= DIST =================
            __shared__ float4 sI[TB * Aa];
            __shared__ float4 sJ[TB * Aa];

            int r = sub, ti = 0;
            while (r >= (TB - ti)) { r -= (TB - ti); ti++; }
            const int tj = ti + r;
            const int i0 = ti * TB, j0 = tj * TB;

            if (t < TB * Aa) {
                const int blk = t / Aa;
                const int at  = t % Aa;
                {
                    const float* p = pos + ((size_t)((b * Ll + i0 + blk) * Aa + at)) * 3;
                    float x = p[0], y = p[1], z = p[2];
                    sI[t] = make_float4(x, y, z, 0.5f * (x * x + y * y + z * z));
                }
                {
                    const float* p = pos + ((size_t)((b * Ll + j0 + blk) * Aa + at)) * 3;
                    float x = p[0], y = p[1], z = p[2];
                    sJ[t] = make_float4(x, y, z, 0.5f * (x * x + y * y + z * z));
                }
            }
            __syncthreads();

            const int ii = t >> 4;
            const int jj = t & 15;

            float jx[Aa], jy[Aa], jz[Aa], jn[Aa];
#pragma unroll
            for (int a = 0; a < Aa; a++) {
                const float4 v = sJ[jj * Aa + a];
                jx[a] = v.x; jy[a] = v.y; jz[a] = v.z; jn[a] = v.w;
            }

            float m0 = CUDART_INF_F, m1 = CUDART_INF_F;
#pragma unroll
            for (int a = 0; a < Aa; a++) {
                const float4 I = sI[ii * Aa + a];
                float mA = fmaf(-I.z, jz[0], fmaf(-I.y, jy[0], fmaf(-I.x, jx[0], jn[0])));
                float mB = fmaf(-I.z, jz[1], fmaf(-I.y, jy[1], fmaf(-I.x, jx[1], jn[1])));
#pragma unroll
                for (int c = 2; c + 1 < Aa; c += 2) {
                    mA = fminf(mA, fmaf(-I.z, jz[c],   fmaf(-I.y, jy[c],   fmaf(-I.x, jx[c],   jn[c]))));
                    mB = fminf(mB, fmaf(-I.z, jz[c+1], fmaf(-I.y, jy[c+1], fmaf(-I.x, jx[c+1], jn[c+1]))));
                }
                mA = fminf(mA, fmaf(-I.z, jz[Aa-1], fmaf(-I.y, jy[Aa-1], fmaf(-I.x, jx[Aa-1], jn[Aa-1]))));
                const float mloc = fminf(mA, mB) + I.w;
                if (a & 1) m1 = fminf(m1, mloc); else m0 = fminf(m0, mloc);
            }
            const float m = fmaxf(fminf(m0, m1), 0.0f);

            float* g = g_d2min + (size_t)b * Ll * Ll;
            g[(size_t)(i0 + ii) * Ll + (j0 + jj)] = m;
            g[(size_t)(j0 + jj) * Ll + (i0 + ii)] = m;

            __syncthreads();
            __threadfence();
            if (t == 0) atomicAdd(&g_cnt[b], 1u);
            return;
        }

        // ================= KNN =================
        {
            const int kcta  = sub - NTILES;             // 0..31
            const int lwarp = (kcta << 3) + (t >> 5);   // 0..255 = l
            const int lane  = t & 31;
            const int l     = lwarp;

            if (t == 0) {
                while (ld_acquire(&g_cnt[b]) < (u32)NTILES) __nanosleep(64);
            }
            __syncthreads();

            const int fi   = frag[(b << 8) + l];
            const int segi = (fi == 2) ? 1 : fi;

            const float* drow = g_d2min + ((size_t)b << 16) + ((size_t)l << 8);
            const int*   frow = frag + (b << 8);

            u64 p0[8], p1[8];
#pragma unroll
            for (int u = 0; u < 8; u++) {
                const int j  = lane + (u << 5);
                const int fj = frow[j];
                const int segj = (fj == 2) ? 1 : fj;
                const bool same = (segj == segi);
                const float v = drow[j];
                const u64 key = ((u64)__float_as_uint(v) << 32) | (u32)j;
                const u64 inf = 0xffffffff00000000ULL | (u32)j;
                p0[u] = (same && j != l) ? key : inf;   // intra
                p1[u] = (!same)          ? key : inf;   // inter
            }

            SORT8(p0)
            SORT8(p1)

            const size_t base0 = (size_t)OFF_EDGES + EDGES_ROW + (size_t)((b << 8) + l) * Kk;
            const size_t base1 = base0 + EDGES_HALF;
            const float  boff  = (float)(b << 8);

#pragma unroll
            for (int k = 0; k < Kk; k++) {
                const u32 hd0 = (u32)(p0[0] >> 32);
                const u32 hd1 = (u32)(p1[0] >> 32);
                const u32 wd0 = __reduce_min_sync(0xffffffffu, hd0);
                const u32 wd1 = __reduce_min_sync(0xffffffffu, hd1);
                const u32 cj0 = (hd0 == wd0) ? (u32)p0[0] : 0xffffffffu;
                const u32 cj1 = (hd1 == wd1) ? (u32)p1[0] : 0xffffffffu;
                const u32 wj0 = __reduce_min_sync(0xffffffffu, cj0);
                const u32 wj1 = __reduce_min_sync(0xffffffffu, cj1);
                if (lane == 0) {
                    out[base0 + k] = (float)wj0 + boff;
                    out[base1 + k] = (float)wj1 + boff;
                }
                if (hd0 == wd0 && (u32)p0[0] == wj0) {
#pragma unroll
                    for (int u = 0; u < 7; u++) p0[u] = p0[u + 1];
                    p0[7] = ~0ULL;
                }
                if (hd1 == wd1 && (u32)p1[0] == wj1) {
#pragma unroll
                    for (int u = 0; u < 7; u++) p1[u] = p1[u + 1];
                    p1[7] = ~0ULL;
                }
            }

            // last knn CTA of this batch resets the counters for the next replay
            __syncthreads();
            if (t == 0) {
                const u32 old = atomicAdd(&g_done[b], 1u);
                if (old == (u32)(KNN_PER_B - 1)) {
                    g_cnt[b]  = 0u;
                    g_done[b] = 0u;
                }
            }
            return;
        }
    }

    // ================= FILL =================
    {
        const int q = (bid - Bb * GROUP) * 256 + t;   // float4 index
        const int i = q << 2;
        if (i >= N_OUT) return;
        float4 v;
        if (i < OFF_BATCH) {
            v.x = (float)(i / Aa); v.y = (float)((i + 1) / Aa);
            v.z = (float)((i + 2) / Aa); v.w = (float)((i + 3) / Aa);
        } else if (i < OFF_EDGES) {
            const float bv = (float)((i - OFF_BATCH) >> 8);
            v.x = bv; v.y = bv; v.z = bv; v.w = bv;
        } else if (i < OFF_ATTR) {
            const int e = i - OFF_EDGES;
            if (e >= EDGES_ROW) return;   // dst row: knn is the SOLE writer
            float s[4];
#pragma unroll
            for (int u = 0; u < 4; u++) {
                const int pu = (e + u) % EDGES_HALF;
                s[u] = (float)(((pu / Kk) % Ll) + (pu / (Ll * Kk)) * Ll);
            }
            v.x = s[0]; v.y = s[1]; v.z = s[2]; v.w = s[3];
        } else {
            const int e    = i - OFF_ATTR;
            const int type = ((e >> 4) >= EDGES_HALF) ? 1 : 0;
            v = *(const float4*)(edge_emb + type * 16 + (e & 12));
        }
        *(float4*)(out + i) = v;
    }
}

// ---------------------------------------------------------------------------
extern "C" void kernel_launch(void* const* d_in, const int* in_sizes, int n_in,
                              void* d_out, int out_size) {
    const float* pos      = (const float*)d_in[0];
    const int*   frag     = (const int*)  d_in[6];
    const float* edge_emb = (const float*)d_in[7];
    float* out = (float*)d_out;

    fused_kernel<<<TOTAL_CTAS, 256>>>(pos, frag, edge_emb, out);

    (void)in_sizes; (void)n_in; (void)out_size;
}